// round 2
// baseline (speedup 1.0000x reference)
#include <cuda_runtime.h>
#include <math.h>

#define B_ 32
#define C_ 256
#define H_ 56
#define W_ 56
#define HW_ (H_*W_)          // 3136
#define R_ 16
#define HW4_ (HW_/4)         // 784
#define NELEM (B_*C_*HW_)

// Scratch
__device__ float g_avg[B_*C_];
__device__ float g_max[B_*C_];
__device__ float g_ca [B_*C_];
__device__ float g_pooled[B_*2*HW_];

// ---------------------------------------------------------------------------
// Kernel 1: per-(b,c) spatial mean & max. One block per (b,c) plane.
// ---------------------------------------------------------------------------
__global__ __launch_bounds__(256) void k_spatial_pool(const float* __restrict__ x) {
    const int bc = blockIdx.x;
    const float4* __restrict__ xp = (const float4*)(x + (size_t)bc * HW_);
    float s = 0.f, m = -INFINITY;
    #pragma unroll 4
    for (int i = threadIdx.x; i < HW4_; i += 256) {
        float4 v = xp[i];
        s += (v.x + v.y) + (v.z + v.w);
        m = fmaxf(m, fmaxf(fmaxf(v.x, v.y), fmaxf(v.z, v.w)));
    }
    #pragma unroll
    for (int o = 16; o > 0; o >>= 1) {
        s += __shfl_xor_sync(0xffffffffu, s, o);
        m = fmaxf(m, __shfl_xor_sync(0xffffffffu, m, o));
    }
    __shared__ float ss[8], sm[8];
    const int w = threadIdx.x >> 5, l = threadIdx.x & 31;
    if (l == 0) { ss[w] = s; sm[w] = m; }
    __syncthreads();
    if (threadIdx.x == 0) {
        float S = ss[0], M = sm[0];
        #pragma unroll
        for (int i = 1; i < 8; i++) { S += ss[i]; M = fmaxf(M, sm[i]); }
        g_avg[bc] = S * (1.0f / HW_);
        g_max[bc] = M;
    }
}

// ---------------------------------------------------------------------------
// Kernel 2: inline MLP (redundant per block) + channel mean/max of x*ca.
// Block = (f4-chunk of 256, batch). float4 loads, unroll 16.
// ---------------------------------------------------------------------------
__global__ __launch_bounds__(256) void k_chan_pool(const float* __restrict__ x,
                                                   const float* __restrict__ w1,
                                                   const float* __restrict__ w2) {
    const int b = blockIdx.y;
    const int t = threadIdx.x;
    __shared__ float sva[C_], svm[C_], hs[R_], sca[C_];

    sva[t] = g_avg[b * C_ + t];
    svm[t] = g_max[b * C_ + t];
    __syncthreads();
    if (t < R_) {
        float ha = 0.f, hm = 0.f;
        const float* __restrict__ wr = w1 + t * C_;
        #pragma unroll 8
        for (int c = 0; c < C_; c++) {
            ha = fmaf(wr[c], sva[c], ha);
            hm = fmaf(wr[c], svm[c], hm);
        }
        hs[t] = fmaxf(ha, 0.f) + fmaxf(hm, 0.f);
    }
    __syncthreads();
    {
        float o = 0.f;
        const float* __restrict__ w2r = w2 + t * R_;
        #pragma unroll
        for (int r = 0; r < R_; r++) o = fmaf(w2r[r], hs[r], o);
        float cav = 1.0f / (1.0f + __expf(-o));
        sca[t] = cav;
        if (blockIdx.x == 0) g_ca[b * C_ + t] = cav;
    }
    __syncthreads();

    const int f4 = blockIdx.x * 256 + t;       // float4 index within plane
    if (f4 >= HW4_) return;
    const float4* __restrict__ xp = (const float4*)(x + (size_t)b * C_ * HW_) + f4;
    float4 s = make_float4(0.f, 0.f, 0.f, 0.f);
    float4 m = make_float4(-INFINITY, -INFINITY, -INFINITY, -INFINITY);
    #pragma unroll 16
    for (int c = 0; c < C_; c++) {
        float4 v = xp[(size_t)c * HW4_];
        const float a = sca[c];
        v.x *= a; v.y *= a; v.z *= a; v.w *= a;
        s.x += v.x; s.y += v.y; s.z += v.z; s.w += v.w;
        m.x = fmaxf(m.x, v.x); m.y = fmaxf(m.y, v.y);
        m.z = fmaxf(m.z, v.z); m.w = fmaxf(m.w, v.w);
    }
    const float inv = 1.0f / C_;
    s.x *= inv; s.y *= inv; s.z *= inv; s.w *= inv;
    float4* __restrict__ pav = (float4*)(g_pooled + (size_t)b * 2 * HW_);
    float4* __restrict__ pmx = (float4*)(g_pooled + (size_t)b * 2 * HW_ + HW_);
    pav[f4] = s;
    pmx[f4] = m;
}

// ---------------------------------------------------------------------------
// Kernel 3: fused 7x7 conv + sigmoid (sa) + final out = x*(1 + ca*sa).
// Block = (row-group of 4, batch). grid (14, 32).
// ---------------------------------------------------------------------------
#define RPB 4                      // rows per block
#define POS_ (RPB*W_)              // 224 sa positions per block
#define F4PB (C_*RPB*(W_/4))       // 14336 float4 per block

__global__ __launch_bounds__(256) void k_final(const float* __restrict__ x,
                                               const float* __restrict__ wsp,
                                               float* __restrict__ out) {
    const int b  = blockIdx.y;
    const int h0 = blockIdx.x * RPB;
    const int t  = threadIdx.x;

    __shared__ float sw[98];
    __shared__ float sca[C_];
    __shared__ float ssa[POS_];

    if (t < 98) sw[t] = wsp[t];
    sca[t] = g_ca[b * C_ + t];
    __syncthreads();

    // conv + sigmoid for this block's 224 positions (pooled is L2-resident)
    if (t < POS_) {
        const int h = h0 + t / W_;
        const int wd = t % W_;
        const float* __restrict__ pa = g_pooled + (size_t)b * 2 * HW_;
        const float* __restrict__ pm = pa + HW_;
        float acc = 0.f;
        #pragma unroll
        for (int kh = 0; kh < 7; kh++) {
            const int hh = h + kh - 3;
            if (hh < 0 || hh >= H_) continue;
            #pragma unroll
            for (int kw = 0; kw < 7; kw++) {
                const int ww = wd + kw - 3;
                if (ww < 0 || ww >= W_) continue;
                const int p = hh * W_ + ww;
                acc = fmaf(sw[kh * 7 + kw],      __ldg(&pa[p]), acc);
                acc = fmaf(sw[49 + kh * 7 + kw], __ldg(&pm[p]), acc);
            }
        }
        ssa[t] = 1.0f / (1.0f + __expf(-acc));
    }
    __syncthreads();

    // apply: out = x * (1 + ca[c] * sa[pos])
    const float4* __restrict__ xb = (const float4*)(x   + (size_t)b * C_ * HW_);
    float4*       __restrict__ ob = (float4*)      (out + (size_t)b * C_ * HW_);
    const int rowbase = h0 * (W_ / 4);             // float4 offset of row group
    #pragma unroll 8
    for (int i = t; i < F4PB; i += 256) {
        const int c    = i / (POS_ / 4);           // i / 56
        const int pos4 = i - c * (POS_ / 4);       // 0..55 (float4 within 4 rows)
        const size_t g = (size_t)c * HW4_ + rowbase + pos4;
        const float ca = sca[c];
        const int sbase = pos4 * 4;
        float4 v = xb[g];
        float4 o;
        o.x = v.x * fmaf(ca, ssa[sbase + 0], 1.0f);
        o.y = v.y * fmaf(ca, ssa[sbase + 1], 1.0f);
        o.z = v.z * fmaf(ca, ssa[sbase + 2], 1.0f);
        o.w = v.w * fmaf(ca, ssa[sbase + 3], 1.0f);
        ob[g] = o;
    }
}

// ---------------------------------------------------------------------------
extern "C" void kernel_launch(void* const* d_in, const int* in_sizes, int n_in,
                              void* d_out, int out_size) {
    const float* x   = (const float*)d_in[0];
    const float* w1  = (const float*)d_in[1];
    const float* w2  = (const float*)d_in[2];
    const float* wsp = (const float*)d_in[3];
    float* out = (float*)d_out;

    k_spatial_pool<<<B_ * C_, 256>>>(x);
    dim3 g2((HW4_ + 255) / 256, B_);               // (4, 32)
    k_chan_pool<<<g2, 256>>>(x, w1, w2);
    dim3 g3(H_ / RPB, B_);                         // (14, 32)
    k_final<<<g3, 256>>>(x, wsp, out);
}

// round 3
// speedup vs baseline: 1.3126x; 1.3126x over previous
#include <cuda_runtime.h>
#include <math.h>

#define B_ 32
#define C_ 256
#define H_ 56
#define W_ 56
#define HW_ (H_*W_)          // 3136
#define R_ 16
#define HW4_ (HW_/4)         // 784
#define CG_ 64               // channels per group
#define NCG_ 4               // channel groups

// Scratch
__device__ float g_avg[B_*C_];
__device__ float g_max[B_*C_];
__device__ float g_ca [B_*C_];
__device__ float g_ps [B_*NCG_*HW_];   // partial channel sums (raw, undivided)
__device__ float g_pm [B_*NCG_*HW_];   // partial channel maxes

// ---------------------------------------------------------------------------
// Kernel 1: per-(b,c) spatial mean & max. One WARP per plane (no block reduce).
// grid 1024 x 256 threads = 8192 warps = 8192 planes.
// ---------------------------------------------------------------------------
__global__ __launch_bounds__(256) void k_spatial_pool(const float* __restrict__ x) {
    const int warp = threadIdx.x >> 5, lane = threadIdx.x & 31;
    const int bc = blockIdx.x * 8 + warp;
    const float4* __restrict__ xp = (const float4*)(x + (size_t)bc * HW_);
    float s = 0.f, m = -INFINITY;
    #pragma unroll 8
    for (int i = lane; i < HW4_; i += 32) {
        float4 v = xp[i];
        s += (v.x + v.y) + (v.z + v.w);
        m = fmaxf(m, fmaxf(fmaxf(v.x, v.y), fmaxf(v.z, v.w)));
    }
    #pragma unroll
    for (int o = 16; o > 0; o >>= 1) {
        s += __shfl_xor_sync(0xffffffffu, s, o);
        m = fmaxf(m, __shfl_xor_sync(0xffffffffu, m, o));
    }
    if (lane == 0) {
        g_avg[bc] = s * (1.0f / HW_);
        g_max[bc] = m;
    }
}

// ---------------------------------------------------------------------------
// Kernel 2: MLP (recomputed per block) + partial channel mean/max of x*ca.
// grid (4 hw-chunks, 4 c-groups, 32 batches) = 512 blocks.
// Each block: 64 channels x up-to-256 float4 positions.
// ---------------------------------------------------------------------------
__global__ __launch_bounds__(256) void k_chan_pool(const float* __restrict__ x,
                                                   const float* __restrict__ w1,
                                                   const float* __restrict__ w2) {
    const int chunk = blockIdx.x, cg = blockIdx.y, b = blockIdx.z;
    const int t = threadIdx.x;
    __shared__ float sva[C_], svm[C_], hs[R_], sca[C_];

    sva[t] = g_avg[b * C_ + t];
    svm[t] = g_max[b * C_ + t];
    __syncthreads();
    if (t < R_) {
        float ha = 0.f, hm = 0.f;
        const float* __restrict__ wr = w1 + t * C_;
        #pragma unroll 8
        for (int c = 0; c < C_; c++) {
            ha = fmaf(wr[c], sva[c], ha);
            hm = fmaf(wr[c], svm[c], hm);
        }
        hs[t] = fmaxf(ha, 0.f) + fmaxf(hm, 0.f);
    }
    __syncthreads();
    {
        float o = 0.f;
        const float* __restrict__ w2r = w2 + t * R_;
        #pragma unroll
        for (int r = 0; r < R_; r++) o = fmaf(w2r[r], hs[r], o);
        float cav = 1.0f / (1.0f + __expf(-o));
        sca[t] = cav;
        if (cg == 0 && chunk == 0) g_ca[b * C_ + t] = cav;
    }
    __syncthreads();

    const int f4 = chunk * 256 + t;
    if (f4 >= HW4_) return;
    const float4* __restrict__ xp =
        (const float4*)(x + (size_t)b * C_ * HW_) + (size_t)cg * CG_ * HW4_ + f4;
    const float* __restrict__ scg = sca + cg * CG_;
    float4 s = make_float4(0.f, 0.f, 0.f, 0.f);
    float4 m = make_float4(-INFINITY, -INFINITY, -INFINITY, -INFINITY);
    #pragma unroll 16
    for (int c = 0; c < CG_; c++) {
        float4 v = xp[(size_t)c * HW4_];
        const float a = scg[c];
        v.x *= a; v.y *= a; v.z *= a; v.w *= a;
        s.x += v.x; s.y += v.y; s.z += v.z; s.w += v.w;
        m.x = fmaxf(m.x, v.x); m.y = fmaxf(m.y, v.y);
        m.z = fmaxf(m.z, v.z); m.w = fmaxf(m.w, v.w);
    }
    const size_t base = ((size_t)b * NCG_ + cg) * HW_;
    ((float4*)(g_ps + base))[f4] = s;
    ((float4*)(g_pm + base))[f4] = m;
}

// ---------------------------------------------------------------------------
// Kernel 3: merge partials + 7x7 conv + sigmoid + out = x*(1 + ca*sa).
// grid (14 row-groups, 32 batches) = 448 blocks.
// ---------------------------------------------------------------------------
#define RPB 4
#define POS_ (RPB*W_)              // 224
#define HALO_ (RPB+6)              // 10 pooled rows needed
#define F4PB (C_*RPB*(W_/4))       // 14336

__global__ __launch_bounds__(256) void k_final(const float* __restrict__ x,
                                               const float* __restrict__ w1,
                                               const float* __restrict__ w2,
                                               const float* __restrict__ wsp,
                                               float* __restrict__ out) {
    const int b  = blockIdx.y;
    const int h0 = blockIdx.x * RPB;
    const int t  = threadIdx.x;

    __shared__ float sw[98], sca[C_], sva[C_], svm[C_], hs[R_];
    __shared__ float spa[HALO_*W_], spm[HALO_*W_], ssa[POS_];

    if (t < 98) sw[t] = wsp[t];
    sva[t] = g_avg[b * C_ + t];
    svm[t] = g_max[b * C_ + t];
    __syncthreads();
    if (t < R_) {
        float ha = 0.f, hm = 0.f;
        const float* __restrict__ wr = w1 + t * C_;
        #pragma unroll 8
        for (int c = 0; c < C_; c++) {
            ha = fmaf(wr[c], sva[c], ha);
            hm = fmaf(wr[c], svm[c], hm);
        }
        hs[t] = fmaxf(ha, 0.f) + fmaxf(hm, 0.f);
    }
    __syncthreads();
    {
        float o = 0.f;
        const float* __restrict__ w2r = w2 + t * R_;
        #pragma unroll
        for (int r = 0; r < R_; r++) o = fmaf(w2r[r], hs[r], o);
        sca[t] = 1.0f / (1.0f + __expf(-o));
    }

    // merge pooled partials into smem halo (L2-resident reads)
    const float* __restrict__ ps = g_ps + (size_t)b * NCG_ * HW_;
    const float* __restrict__ pm = g_pm + (size_t)b * NCG_ * HW_;
    for (int idx = t; idx < HALO_ * W_; idx += 256) {
        const int r = idx / W_;
        const int hh = h0 - 3 + r;
        float av = 0.f, mx = 0.f;
        if (hh >= 0 && hh < H_) {
            const int p = hh * W_ + (idx - r * W_);
            av = (ps[p] + ps[HW_ + p] + ps[2*HW_ + p] + ps[3*HW_ + p]) * (1.0f / C_);
            mx = fmaxf(fmaxf(pm[p], pm[HW_ + p]), fmaxf(pm[2*HW_ + p], pm[3*HW_ + p]));
        }
        spa[idx] = av; spm[idx] = mx;
    }
    __syncthreads();

    if (t < POS_) {
        const int h = h0 + t / W_;
        const int wd = t % W_;
        float acc = 0.f;
        #pragma unroll
        for (int kh = 0; kh < 7; kh++) {
            const int hh = h + kh - 3;
            if (hh < 0 || hh >= H_) continue;
            const int sr = hh - (h0 - 3);
            #pragma unroll
            for (int kw = 0; kw < 7; kw++) {
                const int ww = wd + kw - 3;
                if (ww < 0 || ww >= W_) continue;
                acc = fmaf(sw[kh * 7 + kw],      spa[sr * W_ + ww], acc);
                acc = fmaf(sw[49 + kh * 7 + kw], spm[sr * W_ + ww], acc);
            }
        }
        ssa[t] = 1.0f / (1.0f + __expf(-acc));
    }
    __syncthreads();

    // apply: out = x * (1 + ca[c] * sa[pos])
    const float4* __restrict__ xb = (const float4*)(x   + (size_t)b * C_ * HW_);
    float4*       __restrict__ ob = (float4*)      (out + (size_t)b * C_ * HW_);
    const int rowbase = h0 * (W_ / 4);
    #pragma unroll 8
    for (int i = t; i < F4PB; i += 256) {
        const int c    = i / (POS_ / 4);
        const int pos4 = i - c * (POS_ / 4);
        const size_t g = (size_t)c * HW4_ + rowbase + pos4;
        const float ca = sca[c];
        const int sbase = pos4 * 4;
        float4 v = xb[g];
        float4 o;
        o.x = v.x * fmaf(ca, ssa[sbase + 0], 1.0f);
        o.y = v.y * fmaf(ca, ssa[sbase + 1], 1.0f);
        o.z = v.z * fmaf(ca, ssa[sbase + 2], 1.0f);
        o.w = v.w * fmaf(ca, ssa[sbase + 3], 1.0f);
        ob[g] = o;
    }
}

// ---------------------------------------------------------------------------
extern "C" void kernel_launch(void* const* d_in, const int* in_sizes, int n_in,
                              void* d_out, int out_size) {
    const float* x   = (const float*)d_in[0];
    const float* w1  = (const float*)d_in[1];
    const float* w2  = (const float*)d_in[2];
    const float* wsp = (const float*)d_in[3];
    float* out = (float*)d_out;

    k_spatial_pool<<<1024, 256>>>(x);
    dim3 g2(NCG_, NCG_, B_);                 // (4, 4, 32) = 512 blocks
    k_chan_pool<<<g2, 256>>>(x, w1, w2);
    dim3 g3(H_ / RPB, B_);                   // (14, 32) = 448 blocks
    k_final<<<g3, 256>>>(x, w1, w2, wsp, out);
}

// round 5
// speedup vs baseline: 1.5501x; 1.1809x over previous
#include <cuda_runtime.h>
#include <math.h>

#define B_ 32
#define C_ 256
#define H_ 56
#define W_ 56
#define HW_ (H_*W_)          // 3136
#define R_ 16
#define HW4_ (HW_/4)         // 784
#define CG_ 32               // channels per group
#define NCG_ 8               // channel groups
#define NELEM4 (B_*C_*HW4_)  // 6422528

// Scratch — 16B aligned (accessed via float4)
__device__ __align__(16) float g_avg[B_*C_];
__device__ __align__(16) float g_max[B_*C_];
__device__ __align__(16) float g_ca [B_*C_];
__device__ __align__(16) float g_ps [B_*NCG_*HW_];   // partial channel sums
__device__ __align__(16) float g_pm [B_*NCG_*HW_];   // partial channel maxes
__device__ __align__(16) float g_sa [B_*HW_];

// ---------------------------------------------------------------------------
// Kernel 1: per-(b,c) spatial mean & max. One warp per plane.
// ---------------------------------------------------------------------------
__global__ __launch_bounds__(256) void k_spatial_pool(const float* __restrict__ x) {
    const int warp = threadIdx.x >> 5, lane = threadIdx.x & 31;
    const int bc = blockIdx.x * 8 + warp;
    const float4* __restrict__ xp = (const float4*)(x + (size_t)bc * HW_);
    float s = 0.f, m = -INFINITY;
    #pragma unroll 8
    for (int i = lane; i < HW4_; i += 32) {
        float4 v = xp[i];
        s += (v.x + v.y) + (v.z + v.w);
        m = fmaxf(m, fmaxf(fmaxf(v.x, v.y), fmaxf(v.z, v.w)));
    }
    #pragma unroll
    for (int o = 16; o > 0; o >>= 1) {
        s += __shfl_xor_sync(0xffffffffu, s, o);
        m = fmaxf(m, __shfl_xor_sync(0xffffffffu, m, o));
    }
    if (lane == 0) {
        g_avg[bc] = s * (1.0f / HW_);
        g_max[bc] = m;
    }
}

// ---------------------------------------------------------------------------
// Kernel 2: parallel inline MLP + partial channel mean/max of x*ca.
// grid (4 hw-chunks, 8 c-groups, 32 batches) = 1024 blocks.
// ---------------------------------------------------------------------------
__global__ __launch_bounds__(256) void k_chan_pool(const float* __restrict__ x,
                                                   const float* __restrict__ w1,
                                                   const float* __restrict__ w2) {
    const int chunk = blockIdx.x, cg = blockIdx.y, b = blockIdx.z;
    const int t = threadIdx.x;
    __shared__ float sva[C_], svm[C_], hs[R_], sca[C_];

    sva[t] = g_avg[b * C_ + t];
    svm[t] = g_max[b * C_ + t];
    __syncthreads();

    // Parallel hidden layer: thread t -> hidden unit r = t>>4, channel slice j = t&15.
    {
        const int r = t >> 4, j = t & 15;
        const float* __restrict__ wr = w1 + r * C_ + j * 16;
        const float* __restrict__ va = sva + j * 16;
        const float* __restrict__ vm = svm + j * 16;
        float pa = 0.f, pmx = 0.f;
        #pragma unroll
        for (int i = 0; i < 16; i++) {
            pa  = fmaf(wr[i], va[i], pa);
            pmx = fmaf(wr[i], vm[i], pmx);
        }
        #pragma unroll
        for (int o = 8; o > 0; o >>= 1) {
            pa  += __shfl_down_sync(0xffffffffu, pa,  o, 16);
            pmx += __shfl_down_sync(0xffffffffu, pmx, o, 16);
        }
        if (j == 0) hs[r] = fmaxf(pa, 0.f) + fmaxf(pmx, 0.f);
    }
    __syncthreads();
    {
        float o = 0.f;
        const float* __restrict__ w2r = w2 + t * R_;
        #pragma unroll
        for (int r = 0; r < R_; r++) o = fmaf(w2r[r], hs[r], o);
        float cav = 1.0f / (1.0f + __expf(-o));
        sca[t] = cav;
        if (chunk == 0 && cg == 0) g_ca[b * C_ + t] = cav;
    }
    __syncthreads();

    const int f4 = chunk * 256 + t;
    if (f4 >= HW4_) return;
    const float4* __restrict__ xp =
        (const float4*)(x + (size_t)b * C_ * HW_) + (size_t)cg * CG_ * HW4_ + f4;
    const float* __restrict__ scg = sca + cg * CG_;
    float4 s = make_float4(0.f, 0.f, 0.f, 0.f);
    float4 m = make_float4(-INFINITY, -INFINITY, -INFINITY, -INFINITY);
    #pragma unroll 8
    for (int c = 0; c < CG_; c++) {
        float4 v = xp[(size_t)c * HW4_];
        const float a = scg[c];
        v.x *= a; v.y *= a; v.z *= a; v.w *= a;
        s.x += v.x; s.y += v.y; s.z += v.z; s.w += v.w;
        m.x = fmaxf(m.x, v.x); m.y = fmaxf(m.y, v.y);
        m.z = fmaxf(m.z, v.z); m.w = fmaxf(m.w, v.w);
    }
    const size_t base = ((size_t)b * NCG_ + cg) * HW_;
    ((float4*)(g_ps + base))[f4] = s;
    ((float4*)(g_pm + base))[f4] = m;
}

// ---------------------------------------------------------------------------
// Kernel 3: merge partials (smem tile) + 7x7 conv + sigmoid -> g_sa.
// grid (7 row-tiles of 8, 32 batches) = 224 blocks.
// ---------------------------------------------------------------------------
#define TR 8                       // output rows per block
#define HR (TR + 6)                // halo rows = 14
#define HF4 (HR * W_ / 4)          // 196 float4 in halo tile

__global__ __launch_bounds__(256) void k_sa(const float* __restrict__ wsp) {
    const int b  = blockIdx.y;
    const int h0 = blockIdx.x * TR;
    const int t  = threadIdx.x;

    __shared__ float sw[98];
    __shared__ __align__(16) float spa[HR * W_];
    __shared__ __align__(16) float spm[HR * W_];

    if (t < 98) sw[t] = wsp[t];

    // merge 8 partials into smem halo tile (float4 over rows h0-3 .. h0+10)
    const float* __restrict__ ps = g_ps + (size_t)b * NCG_ * HW_;
    const float* __restrict__ pm = g_pm + (size_t)b * NCG_ * HW_;
    for (int i4 = t; i4 < HF4; i4 += 256) {
        const int r = i4 / (W_ / 4);
        const int hh = h0 - 3 + r;
        float4 s = make_float4(0.f, 0.f, 0.f, 0.f);
        float4 m = make_float4(0.f, 0.f, 0.f, 0.f);
        if (hh >= 0 && hh < H_) {
            const int p4 = hh * (W_ / 4) + (i4 - r * (W_ / 4));
            m = make_float4(-INFINITY, -INFINITY, -INFINITY, -INFINITY);
            #pragma unroll
            for (int g = 0; g < NCG_; g++) {
                float4 vs = ((const float4*)(ps + (size_t)g * HW_))[p4];
                float4 vm = ((const float4*)(pm + (size_t)g * HW_))[p4];
                s.x += vs.x; s.y += vs.y; s.z += vs.z; s.w += vs.w;
                m.x = fmaxf(m.x, vm.x); m.y = fmaxf(m.y, vm.y);
                m.z = fmaxf(m.z, vm.z); m.w = fmaxf(m.w, vm.w);
            }
            const float inv = 1.0f / C_;
            s.x *= inv; s.y *= inv; s.z *= inv; s.w *= inv;
        }
        ((float4*)spa)[i4] = s;
        ((float4*)spm)[i4] = m;
    }
    __syncthreads();

    // conv for TR*W_ = 448 outputs
    for (int p = t; p < TR * W_; p += 256) {
        const int hr = p / W_;            // 0..7
        const int wd = p - hr * W_;
        const int h  = h0 + hr;
        float acc = 0.f;
        #pragma unroll
        for (int kh = 0; kh < 7; kh++) {
            const int hh = h + kh - 3;
            if (hh < 0 || hh >= H_) continue;
            const int sr = hh - (h0 - 3);  // 0..13
            #pragma unroll
            for (int kw = 0; kw < 7; kw++) {
                const int ww = wd + kw - 3;
                if (ww < 0 || ww >= W_) continue;
                acc = fmaf(sw[kh * 7 + kw],      spa[sr * W_ + ww], acc);
                acc = fmaf(sw[49 + kh * 7 + kw], spm[sr * W_ + ww], acc);
            }
        }
        g_sa[b * HW_ + h * W_ + wd] = 1.0f / (1.0f + __expf(-acc));
    }
}

// ---------------------------------------------------------------------------
// Kernel 4: out = x * (1 + ca[b,c] * sa[b,hw]).  Thread per float4.
// ---------------------------------------------------------------------------
__global__ __launch_bounds__(256) void k_final(const float* __restrict__ x,
                                               float* __restrict__ out) {
    const int idx = blockIdx.x * 256 + threadIdx.x;
    if (idx >= NELEM4) return;
    const int bc = idx / HW4_;
    const int q  = idx - bc * HW4_;
    const int b  = bc >> 8;
    const float ca = __ldg(&g_ca[bc]);
    const float4 s = __ldg(((const float4*)(g_sa + (size_t)b * HW_)) + q);
    const float4 v = ((const float4*)x)[idx];
    float4 o;
    o.x = v.x * fmaf(ca, s.x, 1.0f);
    o.y = v.y * fmaf(ca, s.y, 1.0f);
    o.z = v.z * fmaf(ca, s.z, 1.0f);
    o.w = v.w * fmaf(ca, s.w, 1.0f);
    ((float4*)out)[idx] = o;
}

// ---------------------------------------------------------------------------
extern "C" void kernel_launch(void* const* d_in, const int* in_sizes, int n_in,
                              void* d_out, int out_size) {
    const float* x   = (const float*)d_in[0];
    const float* w1  = (const float*)d_in[1];
    const float* w2  = (const float*)d_in[2];
    const float* wsp = (const float*)d_in[3];
    float* out = (float*)d_out;

    k_spatial_pool<<<1024, 256>>>(x);
    dim3 g2((HW4_ + 255) / 256, NCG_, B_);       // (4, 8, 32) = 1024 blocks
    k_chan_pool<<<g2, 256>>>(x, w1, w2);
    dim3 g3(H_ / TR, B_);                        // (7, 32) = 224 blocks
    k_sa<<<g3, 256>>>(wsp);
    k_final<<<(NELEM4 + 255) / 256, 256>>>(x, out);
}

// round 6
// speedup vs baseline: 1.7303x; 1.1163x over previous
#include <cuda_runtime.h>
#include <math.h>

#define B_ 32
#define C_ 256
#define H_ 56
#define W_ 56
#define HW_ (H_*W_)          // 3136
#define R_ 16
#define HW4_ (HW_/4)         // 784
#define QT_ 196              // float4 per thread-stride group (784/4)
#define CG_ 32               // channels per group
#define NCG_ 8               // channel groups
#define NELEM4 (B_*C_*HW4_)  // 6422528

// Scratch — 16B aligned (accessed via float4)
__device__ __align__(16) float g_avg[B_*C_];
__device__ __align__(16) float g_max[B_*C_];
__device__ __align__(16) float g_ca [B_*C_];
__device__ __align__(16) float g_ps [B_*NCG_*HW_];
__device__ __align__(16) float g_pm [B_*NCG_*HW_];
__device__ __align__(16) float g_sa [B_*HW_];

// ---------------------------------------------------------------------------
// Kernel 1: per-(b,c) spatial mean & max. One warp per plane.
// 784 f4 per plane = 32 lanes * 24 + 16 tail. Two front-batched groups of 12.
// ---------------------------------------------------------------------------
__global__ __launch_bounds__(256) void k_spatial_pool(const float* __restrict__ x) {
    const int warp = threadIdx.x >> 5, lane = threadIdx.x & 31;
    const int bc = blockIdx.x * 8 + warp;
    const float4* __restrict__ xp = (const float4*)(x + (size_t)bc * HW_);
    float s = 0.f, m = -INFINITY;
    #pragma unroll
    for (int batch = 0; batch < 2; batch++) {
        float4 v[12];
        #pragma unroll
        for (int j = 0; j < 12; j++) v[j] = xp[lane + 32 * (batch * 12 + j)];
        #pragma unroll
        for (int j = 0; j < 12; j++) {
            s += (v[j].x + v[j].y) + (v[j].z + v[j].w);
            m = fmaxf(m, fmaxf(fmaxf(v[j].x, v[j].y), fmaxf(v[j].z, v[j].w)));
        }
    }
    if (lane < 16) {
        float4 v = xp[768 + lane];
        s += (v.x + v.y) + (v.z + v.w);
        m = fmaxf(m, fmaxf(fmaxf(v.x, v.y), fmaxf(v.z, v.w)));
    }
    #pragma unroll
    for (int o = 16; o > 0; o >>= 1) {
        s += __shfl_xor_sync(0xffffffffu, s, o);
        m = fmaxf(m, __shfl_xor_sync(0xffffffffu, m, o));
    }
    if (lane == 0) {
        g_avg[bc] = s * (1.0f / HW_);
        g_max[bc] = m;
    }
}

// ---------------------------------------------------------------------------
// Kernel 2: parallel inline MLP + partial channel mean/max of x*ca.
// grid (4 hw-chunks, 8 c-groups, 32 batches) = 1024 blocks.
// Channel loop: two front-batched groups of 16 loads.
// ---------------------------------------------------------------------------
__global__ __launch_bounds__(256, 2) void k_chan_pool(const float* __restrict__ x,
                                                      const float* __restrict__ w1,
                                                      const float* __restrict__ w2) {
    const int chunk = blockIdx.x, cg = blockIdx.y, b = blockIdx.z;
    const int t = threadIdx.x;
    __shared__ float sva[C_], svm[C_], hs[R_], sca[C_];

    sva[t] = g_avg[b * C_ + t];
    svm[t] = g_max[b * C_ + t];
    __syncthreads();

    {   // parallel hidden layer: thread t -> (hidden r = t>>4, slice j = t&15)
        const int r = t >> 4, j = t & 15;
        const float* __restrict__ wr = w1 + r * C_ + j * 16;
        const float* __restrict__ va = sva + j * 16;
        const float* __restrict__ vm = svm + j * 16;
        float pa = 0.f, pmx = 0.f;
        #pragma unroll
        for (int i = 0; i < 16; i++) {
            pa  = fmaf(wr[i], va[i], pa);
            pmx = fmaf(wr[i], vm[i], pmx);
        }
        #pragma unroll
        for (int o = 8; o > 0; o >>= 1) {
            pa  += __shfl_down_sync(0xffffffffu, pa,  o, 16);
            pmx += __shfl_down_sync(0xffffffffu, pmx, o, 16);
        }
        if (j == 0) hs[r] = fmaxf(pa, 0.f) + fmaxf(pmx, 0.f);
    }
    __syncthreads();
    {
        float o = 0.f;
        const float* __restrict__ w2r = w2 + t * R_;
        #pragma unroll
        for (int r = 0; r < R_; r++) o = fmaf(w2r[r], hs[r], o);
        float cav = 1.0f / (1.0f + __expf(-o));
        sca[t] = cav;
        if (chunk == 0 && cg == 0) g_ca[b * C_ + t] = cav;
    }
    __syncthreads();

    const int f4 = chunk * 256 + t;
    if (f4 >= HW4_) return;
    const float4* __restrict__ xp =
        (const float4*)(x + (size_t)b * C_ * HW_) + (size_t)cg * CG_ * HW4_ + f4;
    const float* __restrict__ scg = sca + cg * CG_;
    float4 s = make_float4(0.f, 0.f, 0.f, 0.f);
    float4 m = make_float4(-INFINITY, -INFINITY, -INFINITY, -INFINITY);
    #pragma unroll
    for (int batch = 0; batch < 2; batch++) {
        float4 v[16];
        #pragma unroll
        for (int j = 0; j < 16; j++) v[j] = xp[(size_t)(batch * 16 + j) * HW4_];
        #pragma unroll
        for (int j = 0; j < 16; j++) {
            const float a = scg[batch * 16 + j];
            float vx = v[j].x * a, vy = v[j].y * a, vz = v[j].z * a, vw = v[j].w * a;
            s.x += vx; s.y += vy; s.z += vz; s.w += vw;
            m.x = fmaxf(m.x, vx); m.y = fmaxf(m.y, vy);
            m.z = fmaxf(m.z, vz); m.w = fmaxf(m.w, vw);
        }
    }
    const size_t base = ((size_t)b * NCG_ + cg) * HW_;
    ((float4*)(g_ps + base))[f4] = s;
    ((float4*)(g_pm + base))[f4] = m;
}

// ---------------------------------------------------------------------------
// Kernel 3: merge partials (smem tile) + 7x7 conv + sigmoid -> g_sa.
// grid (7 row-tiles of 8, 32 batches) = 224 blocks.
// ---------------------------------------------------------------------------
#define TR 8
#define HR (TR + 6)
#define HF4 (HR * W_ / 4)

__global__ __launch_bounds__(256) void k_sa(const float* __restrict__ wsp) {
    const int b  = blockIdx.y;
    const int h0 = blockIdx.x * TR;
    const int t  = threadIdx.x;

    __shared__ float sw[98];
    __shared__ __align__(16) float spa[HR * W_];
    __shared__ __align__(16) float spm[HR * W_];

    if (t < 98) sw[t] = wsp[t];

    const float* __restrict__ ps = g_ps + (size_t)b * NCG_ * HW_;
    const float* __restrict__ pm = g_pm + (size_t)b * NCG_ * HW_;
    for (int i4 = t; i4 < HF4; i4 += 256) {
        const int r = i4 / (W_ / 4);
        const int hh = h0 - 3 + r;
        float4 s = make_float4(0.f, 0.f, 0.f, 0.f);
        float4 m = make_float4(0.f, 0.f, 0.f, 0.f);
        if (hh >= 0 && hh < H_) {
            const int p4 = hh * (W_ / 4) + (i4 - r * (W_ / 4));
            m = make_float4(-INFINITY, -INFINITY, -INFINITY, -INFINITY);
            #pragma unroll
            for (int g = 0; g < NCG_; g++) {
                float4 vs = ((const float4*)(ps + (size_t)g * HW_))[p4];
                float4 vm = ((const float4*)(pm + (size_t)g * HW_))[p4];
                s.x += vs.x; s.y += vs.y; s.z += vs.z; s.w += vs.w;
                m.x = fmaxf(m.x, vm.x); m.y = fmaxf(m.y, vm.y);
                m.z = fmaxf(m.z, vm.z); m.w = fmaxf(m.w, vm.w);
            }
            const float inv = 1.0f / C_;
            s.x *= inv; s.y *= inv; s.z *= inv; s.w *= inv;
        }
        ((float4*)spa)[i4] = s;
        ((float4*)spm)[i4] = m;
    }
    __syncthreads();

    for (int p = t; p < TR * W_; p += 256) {
        const int hr = p / W_;
        const int wd = p - hr * W_;
        const int h  = h0 + hr;
        float acc = 0.f;
        #pragma unroll
        for (int kh = 0; kh < 7; kh++) {
            const int hh = h + kh - 3;
            if (hh < 0 || hh >= H_) continue;
            const int sr = hh - (h0 - 3);
            #pragma unroll
            for (int kw = 0; kw < 7; kw++) {
                const int ww = wd + kw - 3;
                if (ww < 0 || ww >= W_) continue;
                acc = fmaf(sw[kh * 7 + kw],      spa[sr * W_ + ww], acc);
                acc = fmaf(sw[49 + kh * 7 + kw], spm[sr * W_ + ww], acc);
            }
        }
        g_sa[b * HW_ + h * W_ + wd] = 1.0f / (1.0f + __expf(-acc));
    }
}

// ---------------------------------------------------------------------------
// Kernel 4: out = x * (1 + ca*sa).  4 float4 per thread, stride 196 in-plane.
// grid = B*C*196/256 = 6272 blocks. All loads coalesced; 8 LDG.128 in flight.
// ---------------------------------------------------------------------------
__global__ __launch_bounds__(256) void k_final(const float* __restrict__ x,
                                               float* __restrict__ out) {
    const int g = blockIdx.x * 256 + threadIdx.x;    // 0 .. B*C*196-1
    const int plane = g / QT_;                       // bc
    const int r = g - plane * QT_;                   // 0..195
    const int b = plane >> 8;
    const float ca = __ldg(&g_ca[plane]);
    const float4* __restrict__ xs = (const float4*)x + (size_t)plane * HW4_ + r;
    const float4* __restrict__ ss = (const float4*)(g_sa + (size_t)b * HW_) + r;
    float4*       __restrict__ os = (float4*)out + (size_t)plane * HW4_ + r;

    float4 v0 = xs[0], v1 = xs[QT_], v2 = xs[2*QT_], v3 = xs[3*QT_];
    float4 s0 = __ldg(ss), s1 = __ldg(ss + QT_), s2 = __ldg(ss + 2*QT_), s3 = __ldg(ss + 3*QT_);

    float4 o0, o1, o2, o3;
    o0.x = v0.x * fmaf(ca, s0.x, 1.0f); o0.y = v0.y * fmaf(ca, s0.y, 1.0f);
    o0.z = v0.z * fmaf(ca, s0.z, 1.0f); o0.w = v0.w * fmaf(ca, s0.w, 1.0f);
    o1.x = v1.x * fmaf(ca, s1.x, 1.0f); o1.y = v1.y * fmaf(ca, s1.y, 1.0f);
    o1.z = v1.z * fmaf(ca, s1.z, 1.0f); o1.w = v1.w * fmaf(ca, s1.w, 1.0f);
    o2.x = v2.x * fmaf(ca, s2.x, 1.0f); o2.y = v2.y * fmaf(ca, s2.y, 1.0f);
    o2.z = v2.z * fmaf(ca, s2.z, 1.0f); o2.w = v2.w * fmaf(ca, s2.w, 1.0f);
    o3.x = v3.x * fmaf(ca, s3.x, 1.0f); o3.y = v3.y * fmaf(ca, s3.y, 1.0f);
    o3.z = v3.z * fmaf(ca, s3.z, 1.0f); o3.w = v3.w * fmaf(ca, s3.w, 1.0f);

    os[0] = o0; os[QT_] = o1; os[2*QT_] = o2; os[3*QT_] = o3;
}

// ---------------------------------------------------------------------------
extern "C" void kernel_launch(void* const* d_in, const int* in_sizes, int n_in,
                              void* d_out, int out_size) {
    const float* x   = (const float*)d_in[0];
    const float* w1  = (const float*)d_in[1];
    const float* w2  = (const float*)d_in[2];
    const float* wsp = (const float*)d_in[3];
    float* out = (float*)d_out;

    k_spatial_pool<<<1024, 256>>>(x);
    dim3 g2((HW4_ + 255) / 256, NCG_, B_);       // (4, 8, 32) = 1024 blocks
    k_chan_pool<<<g2, 256>>>(x, w1, w2);
    dim3 g3(H_ / TR, B_);                        // (7, 32) = 224 blocks
    k_sa<<<g3, 256>>>(wsp);
    k_final<<<(B_ * C_ * QT_) / 256, 256>>>(x, out);   // 6272 blocks
}